// round 9
// baseline (speedup 1.0000x reference)
#include <cuda_runtime.h>
#include <cuda_bf16.h>
#include <cstdint>

#define N_NODES 100000
#define N_EDGES 3200000
#define F_IN 256
#define CH 16
#define FCN 64

#define SCAN_B 1024
#define SCAN_NB ((N_NODES + SCAN_B - 1) / SCAN_B)   // 98
#define READY_BIT 0x40000000

#define SCAT_BLOCKS ((N_EDGES + 255) / 256)          // 12500
#define GEMV_WARPS (N_NODES / 2)                     // 50000 (2 nodes/warp)
#define GEMV_BLOCKS (GEMV_WARPS / 8)                 // 6250 (256-thread blocks)

// Scratch: __device__ globals (no allocation allowed). Statically zeroed at
// load; kernels restore zero state each call (scan re-zeros hist; fused
// kernel resets bpub) so graph replays see identical initial conditions.
__device__ __align__(128) float g_h[N_NODES * CH];
__device__ __align__(128) int2  g_rec[N_EDGES];       // (src, w_bits) grouped by dst
__device__ int g_hist[N_NODES];                       // zero-init; re-zeroed in k_scan
__device__ int g_ptr[N_NODES + 1];
__device__ int g_cursor[N_NODES];
__device__ int g_bpub[SCAN_NB];                       // zero-init; reset in k_fused
__device__ int g_idx_is64;                            // published by k_hist

// ---------------------------------------------------------------------------
// log-halving cross-lane reduction of 16 per-channel partials over 32 lanes.
// 16 shfls instead of 80. Channel chan_of_lane(lane) ends on lane (and l^16).
// ---------------------------------------------------------------------------
__device__ __forceinline__ float reduce16(const float* r, int lane) {
    const unsigned FULL = 0xFFFFFFFFu;
    float t[8];
    bool hi = (lane & 1);
#pragma unroll
    for (int j = 0; j < 8; j++) {
        float give = hi ? r[j] : r[j + 8];
        float keep = hi ? r[j + 8] : r[j];
        t[j] = keep + __shfl_xor_sync(FULL, give, 1);
    }
    float u[4];
    hi = (lane & 2);
#pragma unroll
    for (int j = 0; j < 4; j++) {
        float give = hi ? t[j] : t[j + 4];
        float keep = hi ? t[j + 4] : t[j];
        u[j] = keep + __shfl_xor_sync(FULL, give, 2);
    }
    hi = (lane & 4);
    float g0 = hi ? u[0] : u[2];
    float k0 = hi ? u[2] : u[0];
    float v0 = k0 + __shfl_xor_sync(FULL, g0, 4);
    float g1 = hi ? u[1] : u[3];
    float k1 = hi ? u[3] : u[1];
    float v1 = k1 + __shfl_xor_sync(FULL, g1, 4);

    hi = (lane & 8);
    float g2 = hi ? v0 : v1;
    float k2 = hi ? v1 : v0;
    float w = k2 + __shfl_xor_sync(FULL, g2, 8);

    w += __shfl_xor_sync(FULL, w, 16);
    return w;
}

__device__ __forceinline__ int chan_of_lane(int lane) {
    return ((lane & 1) << 3) | ((lane & 2) << 1) | ((lane & 4) >> 1) | ((lane & 8) >> 3);
}

// ---------------------------------------------------------------------------
// Launch 1: histogram of destinations + dtype probe. Lean: one edge/thread.
// ---------------------------------------------------------------------------
__global__ void k_hist(const int* __restrict__ ei32, int E) {
    const unsigned FULL = 0xFFFFFFFFu;
    const int gtid = blockIdx.x * blockDim.x + threadIdx.x;
    const int lane = threadIdx.x & 31;

    // Per-warp dtype probe: odd words 1..63 are 0 iff int64 layout.
    int oddw = ei32[2 * lane + 1];
    unsigned nz = __ballot_sync(FULL, oddw != 0);
    const bool is64 = (nz == 0);
    if (gtid == 0) g_idx_is64 = is64 ? 1 : 0;

    if (gtid >= E) return;
    int dst = is64 ? ei32[(size_t)2 * (E + gtid)] : ei32[(size_t)E + gtid];
    atomicAdd(&g_hist[dst], 1);   // no return -> RED
}

// ---------------------------------------------------------------------------
// Launch 2: single-pass scan (decoupled lookback). 98 blocks all resident
// (98 < 148 SMs) -> publish-then-spin cannot deadlock. Re-zeros g_hist.
// ---------------------------------------------------------------------------
__global__ void k_scan() {
    __shared__ int s[SCAN_B];
    __shared__ int s_off;
    const int t = threadIdx.x;
    const int b = blockIdx.x;
    const int idx = b * SCAN_B + t;

    int v = 0;
    if (idx < N_NODES) {
        v = g_hist[idx];
        g_hist[idx] = 0;                 // restore zero state for next call
    }
    s[t] = v;
    __syncthreads();
#pragma unroll
    for (int off = 1; off < SCAN_B; off <<= 1) {
        int u = (t >= off) ? s[t - off] : 0;
        __syncthreads();
        s[t] += u;
        __syncthreads();
    }

    if (t == 0) {
        s_off = 0;
        atomicExch(&g_bpub[b], s[SCAN_B - 1] | READY_BIT);   // publish own total
    }
    __syncthreads();

    if (t < b) {
        int u;
        do { u = atomicAdd(&g_bpub[t], 0); } while (!(u & READY_BIT));
        atomicAdd(&s_off, u & ~READY_BIT);
    }
    __syncthreads();

    int p = s[t] - v + s_off;            // global exclusive prefix
    if (idx < N_NODES) {
        g_ptr[idx] = p;
        g_cursor[idx] = p;
    }
    if (b == SCAN_NB - 1 && t == SCAN_B - 1)
        g_ptr[N_NODES] = s[t] + s_off;   // == E
}

// ---------------------------------------------------------------------------
// Launch 3 (FUSED, block-role split):
//   blocks [0, SCAT_BLOCKS): scatter edges into CSR records (L2/atomic-bound)
//   blocks [SCAT_BLOCKS, +GEMV_BLOCKS): h = x @ w_gcn, 2 nodes/warp (FMA-bound)
// Disjoint pipes -> GEMV hides under scatter's memory time.
// ---------------------------------------------------------------------------
__global__ void __launch_bounds__(256) k_fused(
        const float* __restrict__ x, const float* __restrict__ w_gcn,
        const int* __restrict__ ei32, const float* __restrict__ ew, int E) {
    __shared__ __align__(16) float w_t[F_IN * CH];   // [c][k], pitch 256
    const int tid = threadIdx.x;

    if (blockIdx.x < SCAT_BLOCKS) {
        // ------------------ scatter role ------------------
        if (blockIdx.x == 0 && tid < SCAN_NB) g_bpub[tid] = 0;  // reset flags

        int e = blockIdx.x * 256 + tid;
        if (e >= E) return;

        int src, dst;
        if (g_idx_is64) {
            src = ei32[(size_t)2 * e];
            dst = ei32[(size_t)2 * (E + e)];
        } else {
            src = ei32[e];
            dst = ei32[(size_t)E + e];
        }
        float w = ew[e];

        int p = atomicAdd(&g_cursor[dst], 1);
        g_rec[p] = make_int2(src, __float_as_int(w));
        return;
    }

    // ------------------ GEMV role: 2 nodes per warp ------------------
    for (int i = tid; i < F_IN * CH; i += 256) {
        int k = i >> 4;
        int c = i & 15;
        w_t[c * F_IN + k] = w_gcn[i];
    }
    __syncthreads();

    const int gb = blockIdx.x - SCAT_BLOCKS;
    const int warp = gb * 8 + (tid >> 5);
    const int lane = tid & 31;
    const int n0 = warp * 2;
    if (n0 >= N_NODES) return;

    const float4* __restrict__ xr4 = (const float4*)(x + (size_t)n0 * F_IN);
    const float4* wt4 = (const float4*)w_t;          // [c][k4], pitch 64

    float acc0[CH], acc1[CH];
#pragma unroll
    for (int c = 0; c < CH; c++) { acc0[c] = acc1[c] = 0.f; }

#pragma unroll
    for (int i = 0; i < 2; i++) {
        int k4 = i * 32 + lane;                      // float4 column index
        float4 xa = xr4[k4];                         // LDG.128, coalesced
        float4 xb = xr4[64 + k4];
#pragma unroll
        for (int c = 0; c < CH; c++) {
            float4 wv = wt4[c * 64 + k4];            // LDS.128, conflict-free
            acc0[c] += xa.x * wv.x + xa.y * wv.y + xa.z * wv.z + xa.w * wv.w;
            acc1[c] += xb.x * wv.x + xb.y * wv.y + xb.z * wv.z + xb.w * wv.w;
        }
    }

    const int chan = chan_of_lane(lane);
    float s0 = reduce16(acc0, lane);
    float s1 = reduce16(acc1, lane);
    if (lane < 16) {
        g_h[(size_t)(n0 + 0) * CH + chan] = s0;
        g_h[(size_t)(n0 + 1) * CH + chan] = s1;
    }
}

// ---------------------------------------------------------------------------
// Launch 4: atomic-free aggregation FUSED with FCN head. One warp per node.
// ---------------------------------------------------------------------------
__global__ void k2d_agg_head(const float* __restrict__ w0, const float* __restrict__ b0,
                             const float* __restrict__ w1, const float* __restrict__ b1,
                             float* __restrict__ out) {
    __shared__ float s_w0[CH * FCN];    // [c][f]: lane-consecutive reads
    __shared__ float s_w1[FCN];
    __shared__ float s_b0[FCN];
    __shared__ float s_b1;
    const int tid = threadIdx.x;
    for (int i = tid; i < CH * FCN; i += blockDim.x) s_w0[i] = w0[i];
    for (int i = tid; i < FCN; i += blockDim.x) { s_w1[i] = w1[i]; s_b0[i] = b0[i]; }
    if (tid == 0) s_b1 = b1[0];
    __syncthreads();

    const unsigned FULL = 0xFFFFFFFFu;
    int gtid = blockIdx.x * blockDim.x + tid;
    int n = gtid >> 5;
    if (n >= N_NODES) return;
    int lane = tid & 31;
    int slot = lane >> 2;     // 0..7 : edge slot within a group of 8
    int j = lane & 3;         // 0..3 : which float4 of the 16-ch row

    int start = g_ptr[n];
    int end = g_ptr[n + 1];

    float ax = 0.f, ay = 0.f, az = 0.f, aw = 0.f;

    for (int base = start; base < end; base += 32) {
#pragma unroll
        for (int g = 0; g < 4; g++) {
            int idx = base + g * 8 + slot;
            if (idx < end) {
                int2 r = g_rec[idx];                   // 4 lanes same addr: bcast
                float w = __int_as_float(r.y);
                const float4 hv = *(const float4*)(g_h + (size_t)r.x * CH + j * 4);
                ax += hv.x * w; ay += hv.y * w; az += hv.z * w; aw += hv.w * w;
            }
        }
    }

    // Reduce across the 8 edge-slots: lanes 0-3 hold the 16 channels
#pragma unroll
    for (int m = 4; m <= 16; m <<= 1) {
        ax += __shfl_xor_sync(FULL, ax, m);
        ay += __shfl_xor_sync(FULL, ay, m);
        az += __shfl_xor_sync(FULL, az, m);
        aw += __shfl_xor_sync(FULL, aw, m);
    }

    // Broadcast the 16 channels (relu'd) to all lanes
    float a[CH];
#pragma unroll
    for (int q = 0; q < 4; q++) {
        a[4 * q + 0] = fmaxf(__shfl_sync(FULL, ax, q), 0.f);
        a[4 * q + 1] = fmaxf(__shfl_sync(FULL, ay, q), 0.f);
        a[4 * q + 2] = fmaxf(__shfl_sync(FULL, az, q), 0.f);
        a[4 * q + 3] = fmaxf(__shfl_sync(FULL, aw, q), 0.f);
    }

    // FCN head: lane l computes units f=l and f=l+32.
    float o1a = s_b0[lane];
    float o1b = s_b0[lane + 32];
#pragma unroll
    for (int c = 0; c < CH; c++) {
        o1a += a[c] * s_w0[c * FCN + lane];        // conflict-free LDS
        o1b += a[c] * s_w0[c * FCN + lane + 32];
    }
    o1a = fmaxf(o1a, 0.f);
    o1b = fmaxf(o1b, 0.f);
    float o2 = o1a * s_w1[lane] + o1b * s_w1[lane + 32];
#pragma unroll
    for (int m = 16; m > 0; m >>= 1)
        o2 += __shfl_xor_sync(FULL, o2, m);
    if (lane == 0) out[n] = o2 + s_b1;
}

// ---------------------------------------------------------------------------
// Launcher. Inputs identified by element count (robust to ordering):
//   x: 25,600,000   edge_index: 6,400,000   edge_w: 3,200,000
//   w_gcn: 4096     w0: 1024   b0: 64 (first)   w1: 64 (second)   b1: 1
// ---------------------------------------------------------------------------
extern "C" void kernel_launch(void* const* d_in, const int* in_sizes, int n_in,
                              void* d_out, int out_size) {
    const float* x = nullptr;
    const int* ei = nullptr;
    const float* ew = nullptr;
    const float* wg = nullptr;
    const float* w0 = nullptr;
    const float* b0 = nullptr;
    const float* w1 = nullptr;
    const float* b1 = nullptr;
    int E = 0;
    int seen64 = 0;

    for (int i = 0; i < n_in; i++) {
        int s = in_sizes[i];
        if (s == N_NODES * F_IN)      x  = (const float*)d_in[i];
        else if (s == 2 * N_EDGES)    { ei = (const int*)d_in[i]; E = s / 2; }
        else if (s == N_EDGES)        ew = (const float*)d_in[i];
        else if (s == F_IN * CH)      wg = (const float*)d_in[i];
        else if (s == CH * FCN)       w0 = (const float*)d_in[i];
        else if (s == FCN)            { if (seen64++ == 0) b0 = (const float*)d_in[i];
                                        else               w1 = (const float*)d_in[i]; }
        else if (s == 1)              b1 = (const float*)d_in[i];
    }

    float* out = (float*)d_out;

    // Launch 1: histogram + dtype probe
    k_hist<<<(N_EDGES + 255) / 256, 256>>>(ei, E);

    // Launch 2: single-pass lookback scan (+ hist re-zero)
    k_scan<<<SCAN_NB, SCAN_B>>>();

    // Launch 3: fused scatter (L2-bound) + GEMV (FMA-bound) overlap
    k_fused<<<SCAT_BLOCKS + GEMV_BLOCKS, 256>>>(x, wg, ei, ew, E);

    // Launch 4: atomic-free aggregation + FCN head, warp per node
    k2d_agg_head<<<(N_NODES * 32 + 255) / 256, 256>>>(w0, b0, w1, b1, out);
}

// round 10
// speedup vs baseline: 1.1101x; 1.1101x over previous
#include <cuda_runtime.h>
#include <cuda_bf16.h>
#include <cstdint>

#define N_NODES 100000
#define N_EDGES 3200000
#define F_IN 256
#define CH 16
#define FCN 64

#define SCAN_B 1024
#define SCAN_NB ((N_NODES + SCAN_B - 1) / SCAN_B)   // 98
#define READY_BIT 0x40000000

#define REC_CAP (N_EDGES + 8 * N_NODES)              // padded CSR capacity
#define SCAT_BLOCKS ((N_EDGES + 255) / 256)          // 12500
#define GEMV_WARPS (N_NODES / 4)                     // 25000 (4 nodes/warp)
#define GEMV_BLOCKS (GEMV_WARPS / 8)                 // 3125
#define FUSED_BLOCKS (SCAT_BLOCKS + GEMV_BLOCKS)     // 15625 (= 5 * 3125)

// Scratch: __device__ globals (no allocation allowed). Statically zeroed at
// load; kernels restore zero state each call (scan re-zeros hist; fused
// resets bpub). CSR padding slots are never written -> stay (0,0) forever:
// src_off=0, w=0 contributes nothing (gathers L1-hot row 0).
__device__ __align__(128) float g_h[N_NODES * CH];
__device__ __align__(128) int2  g_rec[REC_CAP];       // (src*64, w_bits), dst-grouped
__device__ int g_hist[N_NODES];                       // zero-init; re-zeroed in k_scan
__device__ int g_ptr[N_NODES + 1];                    // padded-degree prefix
__device__ int g_cursor[N_NODES];
__device__ int g_bpub[SCAN_NB];                       // zero-init; reset in k_fused
__device__ int g_idx_is64;                            // published by k_hist

// ---------------------------------------------------------------------------
// log-halving cross-lane reduction of 16 per-channel partials over 32 lanes.
// 16 shfls instead of 80. Channel chan_of_lane(lane) ends on lane (and l^16).
// ---------------------------------------------------------------------------
__device__ __forceinline__ float reduce16(const float* r, int lane) {
    const unsigned FULL = 0xFFFFFFFFu;
    float t[8];
    bool hi = (lane & 1);
#pragma unroll
    for (int j = 0; j < 8; j++) {
        float give = hi ? r[j] : r[j + 8];
        float keep = hi ? r[j + 8] : r[j];
        t[j] = keep + __shfl_xor_sync(FULL, give, 1);
    }
    float u[4];
    hi = (lane & 2);
#pragma unroll
    for (int j = 0; j < 4; j++) {
        float give = hi ? t[j] : t[j + 4];
        float keep = hi ? t[j + 4] : t[j];
        u[j] = keep + __shfl_xor_sync(FULL, give, 2);
    }
    hi = (lane & 4);
    float g0 = hi ? u[0] : u[2];
    float k0 = hi ? u[2] : u[0];
    float v0 = k0 + __shfl_xor_sync(FULL, g0, 4);
    float g1 = hi ? u[1] : u[3];
    float k1 = hi ? u[3] : u[1];
    float v1 = k1 + __shfl_xor_sync(FULL, g1, 4);

    hi = (lane & 8);
    float g2 = hi ? v0 : v1;
    float k2 = hi ? v1 : v0;
    float w = k2 + __shfl_xor_sync(FULL, g2, 8);

    w += __shfl_xor_sync(FULL, w, 16);
    return w;
}

__device__ __forceinline__ int chan_of_lane(int lane) {
    return ((lane & 1) << 3) | ((lane & 2) << 1) | ((lane & 4) >> 1) | ((lane & 8) >> 3);
}

// ---------------------------------------------------------------------------
// Launch 1: histogram of destinations + dtype probe. One edge per thread.
// ---------------------------------------------------------------------------
__global__ void k_hist(const int* __restrict__ ei32, int E) {
    const unsigned FULL = 0xFFFFFFFFu;
    const int gtid = blockIdx.x * blockDim.x + threadIdx.x;
    const int lane = threadIdx.x & 31;

    // Per-warp dtype probe: odd words 1..63 are 0 iff int64 layout.
    int oddw = ei32[2 * lane + 1];
    unsigned nz = __ballot_sync(FULL, oddw != 0);
    const bool is64 = (nz == 0);
    if (gtid == 0) g_idx_is64 = is64 ? 1 : 0;

    if (gtid >= E) return;
    int dst = is64 ? ei32[(size_t)2 * (E + gtid)] : ei32[(size_t)E + gtid];
    atomicAdd(&g_hist[dst], 1);   // no return -> RED
}

// ---------------------------------------------------------------------------
// Launch 2: single-pass scan (decoupled lookback) over PADDED degrees
// (pad to multiple of 8 -> branch-free k2d). 98 blocks all resident
// (98 < 148 SMs) -> publish-then-spin cannot deadlock. Re-zeros g_hist.
// ---------------------------------------------------------------------------
__global__ void k_scan() {
    __shared__ int s[SCAN_B];
    __shared__ int s_off;
    const int t = threadIdx.x;
    const int b = blockIdx.x;
    const int idx = b * SCAN_B + t;

    int v = 0;
    if (idx < N_NODES) {
        int d = g_hist[idx];
        g_hist[idx] = 0;                 // restore zero state for next call
        v = (d + 7) & ~7;                // padded degree
    }
    s[t] = v;
    __syncthreads();
#pragma unroll
    for (int off = 1; off < SCAN_B; off <<= 1) {
        int u = (t >= off) ? s[t - off] : 0;
        __syncthreads();
        s[t] += u;
        __syncthreads();
    }

    if (t == 0) {
        s_off = 0;
        atomicExch(&g_bpub[b], s[SCAN_B - 1] | READY_BIT);   // publish own total
    }
    __syncthreads();

    if (t < b) {
        int u;
        do { u = atomicAdd(&g_bpub[t], 0); } while (!(u & READY_BIT));
        atomicAdd(&s_off, u & ~READY_BIT);
    }
    __syncthreads();

    int p = s[t] - v + s_off;            // global exclusive prefix (padded)
    if (idx < N_NODES) {
        g_ptr[idx] = p;
        g_cursor[idx] = p;
    }
    if (b == SCAN_NB - 1 && t == SCAN_B - 1)
        g_ptr[N_NODES] = s[t] + s_off;
}

// ---------------------------------------------------------------------------
// Launch 3 (FUSED, INTERLEAVED roles): blockIdx.x % 5 == 4 -> GEMV (3125
// blocks, 4 nodes/warp); else scatter (12500 blocks). Interleaving puts both
// roles in every wave -> scatter (LTS/atomic pipe) and GEMV (FMA/LDS pipe)
// co-run on disjoint hardware.
// ---------------------------------------------------------------------------
__global__ void __launch_bounds__(256) k_fused(
        const float* __restrict__ x, const float* __restrict__ w_gcn,
        const int* __restrict__ ei32, const float* __restrict__ ew, int E) {
    __shared__ __align__(16) float w_t[F_IN * CH];   // [c][k], pitch 256
    const int tid = threadIdx.x;
    const int bid = blockIdx.x;
    const int q5 = bid / 5;

    if ((bid % 5) != 4) {
        // ------------------ scatter role ------------------
        const int sbid = bid - q5;                    // 0..12499
        if (sbid == 0 && tid < SCAN_NB) g_bpub[tid] = 0;  // reset lookback flags

        int e = sbid * 256 + tid;
        if (e >= E) return;

        int src, dst;
        if (g_idx_is64) {
            src = ei32[(size_t)2 * e];
            dst = ei32[(size_t)2 * (E + e)];
        } else {
            src = ei32[e];
            dst = ei32[(size_t)E + e];
        }
        float w = ew[e];

        int p = atomicAdd(&g_cursor[dst], 1);
        g_rec[p] = make_int2(src << 6, __float_as_int(w));  // pre-scaled byte offset
        return;
    }

    // ------------------ GEMV role: 4 nodes per warp ------------------
    for (int i = tid; i < F_IN * CH; i += 256) {
        int k = i >> 4;
        int c = i & 15;
        w_t[c * F_IN + k] = w_gcn[i];
    }
    __syncthreads();

    const int warp = q5 * 8 + (tid >> 5);            // 0..24999
    const int lane = tid & 31;
    const int n0 = warp * 4;
    if (n0 >= N_NODES) return;

    const float4* __restrict__ xr4 = (const float4*)(x + (size_t)n0 * F_IN);
    const float4* wt4 = (const float4*)w_t;          // [c][k4], pitch 64

    float acc0[CH], acc1[CH], acc2[CH], acc3[CH];
#pragma unroll
    for (int c = 0; c < CH; c++) { acc0[c] = acc1[c] = acc2[c] = acc3[c] = 0.f; }

#pragma unroll
    for (int i = 0; i < 2; i++) {
        int k4 = i * 32 + lane;                      // float4 column index
        float4 xa = xr4[k4];                         // LDG.128, coalesced
        float4 xb = xr4[64 + k4];
        float4 xc = xr4[128 + k4];
        float4 xd = xr4[192 + k4];
#pragma unroll
        for (int c = 0; c < CH; c++) {
            float4 wv = wt4[c * 64 + k4];            // LDS.128, conflict-free
            acc0[c] += xa.x * wv.x + xa.y * wv.y + xa.z * wv.z + xa.w * wv.w;
            acc1[c] += xb.x * wv.x + xb.y * wv.y + xb.z * wv.z + xb.w * wv.w;
            acc2[c] += xc.x * wv.x + xc.y * wv.y + xc.z * wv.z + xc.w * wv.w;
            acc3[c] += xd.x * wv.x + xd.y * wv.y + xd.z * wv.z + xd.w * wv.w;
        }
    }

    const int chan = chan_of_lane(lane);
    float s0 = reduce16(acc0, lane);
    float s1 = reduce16(acc1, lane);
    float s2 = reduce16(acc2, lane);
    float s3 = reduce16(acc3, lane);
    if (lane < 16) {
        g_h[(size_t)(n0 + 0) * CH + chan] = s0;
        g_h[(size_t)(n0 + 1) * CH + chan] = s1;
        g_h[(size_t)(n0 + 2) * CH + chan] = s2;
        g_h[(size_t)(n0 + 3) * CH + chan] = s3;
    }
}

// ---------------------------------------------------------------------------
// Launch 4: atomic-free aggregation FUSED with FCN head. One warp per node.
// Padded CSR (multiple of 8) -> branch-free uniform loop: group slot=lane>>2
// handles edge start+slot, step 8. Records hold src*64 -> gather address is
// one IADD. Padding records (0,0) gather L1-hot row 0 with w=0.
// ---------------------------------------------------------------------------
__global__ void k2d_agg_head(const float* __restrict__ w0, const float* __restrict__ b0,
                             const float* __restrict__ w1, const float* __restrict__ b1,
                             float* __restrict__ out) {
    __shared__ float s_w0[CH * FCN];    // [c][f]: lane-consecutive reads
    __shared__ float s_w1[FCN];
    __shared__ float s_b0[FCN];
    __shared__ float s_b1;
    const int tid = threadIdx.x;
    for (int i = tid; i < CH * FCN; i += blockDim.x) s_w0[i] = w0[i];
    for (int i = tid; i < FCN; i += blockDim.x) { s_w1[i] = w1[i]; s_b0[i] = b0[i]; }
    if (tid == 0) s_b1 = b1[0];
    __syncthreads();

    const unsigned FULL = 0xFFFFFFFFu;
    int gtid = blockIdx.x * blockDim.x + tid;
    int n = gtid >> 5;
    if (n >= N_NODES) return;
    int lane = tid & 31;
    int slot = lane >> 2;               // 0..7
    const char* hbase = (const char*)g_h + ((lane & 3) << 4);

    int start = g_ptr[n];
    int end = g_ptr[n + 1];             // end-start is a multiple of 8

    float ax = 0.f, ay = 0.f, az = 0.f, aw = 0.f;

#pragma unroll 2
    for (int idx = start + slot; idx < end; idx += 8) {
        int2 r = g_rec[idx];                           // 4 lanes same addr: bcast
        float w = __int_as_float(r.y);
        const float4 hv = *(const float4*)(hbase + r.x);
        ax += hv.x * w; ay += hv.y * w; az += hv.z * w; aw += hv.w * w;
    }

    // Reduce across the 8 edge-slots: lanes 0-3 hold the 16 channels
#pragma unroll
    for (int m = 4; m <= 16; m <<= 1) {
        ax += __shfl_xor_sync(FULL, ax, m);
        ay += __shfl_xor_sync(FULL, ay, m);
        az += __shfl_xor_sync(FULL, az, m);
        aw += __shfl_xor_sync(FULL, aw, m);
    }

    // Broadcast the 16 channels (relu'd) to all lanes
    float a[CH];
#pragma unroll
    for (int q = 0; q < 4; q++) {
        a[4 * q + 0] = fmaxf(__shfl_sync(FULL, ax, q), 0.f);
        a[4 * q + 1] = fmaxf(__shfl_sync(FULL, ay, q), 0.f);
        a[4 * q + 2] = fmaxf(__shfl_sync(FULL, az, q), 0.f);
        a[4 * q + 3] = fmaxf(__shfl_sync(FULL, aw, q), 0.f);
    }

    // FCN head: lane l computes units f=l and f=l+32.
    float o1a = s_b0[lane];
    float o1b = s_b0[lane + 32];
#pragma unroll
    for (int c = 0; c < CH; c++) {
        o1a += a[c] * s_w0[c * FCN + lane];        // conflict-free LDS
        o1b += a[c] * s_w0[c * FCN + lane + 32];
    }
    o1a = fmaxf(o1a, 0.f);
    o1b = fmaxf(o1b, 0.f);
    float o2 = o1a * s_w1[lane] + o1b * s_w1[lane + 32];
#pragma unroll
    for (int m = 16; m > 0; m >>= 1)
        o2 += __shfl_xor_sync(FULL, o2, m);
    if (lane == 0) out[n] = o2 + s_b1;
}

// ---------------------------------------------------------------------------
// Launcher. Inputs identified by element count (robust to ordering):
//   x: 25,600,000   edge_index: 6,400,000   edge_w: 3,200,000
//   w_gcn: 4096     w0: 1024   b0: 64 (first)   w1: 64 (second)   b1: 1
// ---------------------------------------------------------------------------
extern "C" void kernel_launch(void* const* d_in, const int* in_sizes, int n_in,
                              void* d_out, int out_size) {
    const float* x = nullptr;
    const int* ei = nullptr;
    const float* ew = nullptr;
    const float* wg = nullptr;
    const float* w0 = nullptr;
    const float* b0 = nullptr;
    const float* w1 = nullptr;
    const float* b1 = nullptr;
    int E = 0;
    int seen64 = 0;

    for (int i = 0; i < n_in; i++) {
        int s = in_sizes[i];
        if (s == N_NODES * F_IN)      x  = (const float*)d_in[i];
        else if (s == 2 * N_EDGES)    { ei = (const int*)d_in[i]; E = s / 2; }
        else if (s == N_EDGES)        ew = (const float*)d_in[i];
        else if (s == F_IN * CH)      wg = (const float*)d_in[i];
        else if (s == CH * FCN)       w0 = (const float*)d_in[i];
        else if (s == FCN)            { if (seen64++ == 0) b0 = (const float*)d_in[i];
                                        else               w1 = (const float*)d_in[i]; }
        else if (s == 1)              b1 = (const float*)d_in[i];
    }

    float* out = (float*)d_out;

    // Launch 1: histogram + dtype probe
    k_hist<<<(N_EDGES + 255) / 256, 256>>>(ei, E);

    // Launch 2: single-pass lookback scan over padded degrees (+ hist re-zero)
    k_scan<<<SCAN_NB, SCAN_B>>>();

    // Launch 3: interleaved scatter (L2-bound) + GEMV (FMA-bound)
    k_fused<<<FUSED_BLOCKS, 256>>>(x, wg, ei, ew, E);

    // Launch 4: atomic-free aggregation + FCN head, warp per node
    k2d_agg_head<<<(N_NODES * 32 + 255) / 256, 256>>>(w0, b0, w1, b1, out);
}